// round 13
// baseline (speedup 1.0000x reference)
#include <cuda_runtime.h>
#include <cstdint>
#include <math.h>

#define BB 8
#define SS 2048
#define TT 16384

// ---------------- fp32 scratch ----------------
#define F_QKV  0u            // 16384*384
#define F_QKV2 6291456u      // 16384*384
#define F_ATT  12582912u     // 16384*128
#define F_ATT2 14680064u
#define F_BUFB 16777216u
#define F_BUFH 18874368u     // 16384*512
#define F_BUFC 27262976u
#define F_SE   29360128u
#define F_SN   31457280u
#define F_TE   33554432u
#define F_TN   35651584u
#define F_M    37748736u     // 8*128*128
#define F_SIM  37879808u     // 16384
#define F_TOT  37896192u
__device__ float g_f32[F_TOT];

enum { EP_F32 = 0, EP_LN = 1, EP_GELU = 2, EP_LN2 = 3, EP_COS = 4, EP_FINAL = 5, EP_SIMDOT = 6 };

__device__ __forceinline__ uint32_t smem_to_u32(const void* p) {
    uint32_t a;
    asm("{ .reg .u64 t; cvta.to.shared.u64 t, %1; cvt.u32.u64 %0, t; }" : "=r"(a) : "l"(p));
    return a;
}

#define CP16(dst, src) do { \
    unsigned long long _gs = (unsigned long long)__cvta_generic_to_global((const void*)(src)); \
    asm volatile("cp.async.cg.shared.global [%0], [%1], 16;" :: "r"(dst), "l"(_gs)); } while (0)
#define CP_COMMIT() asm volatile("cp.async.commit_group;" ::: "memory")
#define CP_WAIT(n) asm volatile("cp.async.wait_group %0;" :: "n"(n) : "memory")

// tf32 mma: D(16x8) += A(16x8) * B(8x8); raw f32 regs truncated to tf32 by HW
#define MMA_TF32(c, a, b) \
    asm volatile("mma.sync.aligned.m16n8k8.row.col.f32.tf32.tf32.f32 " \
        "{%0,%1,%2,%3}, {%4,%5,%6,%7}, {%8,%9}, {%0,%1,%2,%3};" \
        : "+f"((c)[0]), "+f"((c)[1]), "+f"((c)[2]), "+f"((c)[3]) \
        : "r"((a)[0]), "r"((a)[1]), "r"((a)[2]), "r"((a)[3]), "r"((b)[0]), "r"((b)[1]))

__device__ __forceinline__ float gelu_f(float v) {
    return 0.5f * v * (1.0f + erff(v * 0.70710678118654752f));
}

__global__ void zero_k(float* p, int n)
{
    int i = blockIdx.x * 256 + threadIdx.x;
    if (i < n) p[i] = 0.f;
}

// ============== generic tf32 GEMM: C[M,N] = A @ W^T ==============
// Tile 64(M) x 128(N), 256 threads = 8 warps (2 wm x 4 wn), warp tile 32x32.
// smem stage (27648B): A +0 (64 rows x 36 floats), B +9216 (128 rows x 36 floats).
// 3-stage cp.async pipeline (prefetch distance 2 chunks). Dual-problem mode optional.
#define GSTT 27648
__global__ void __launch_bounds__(256, 2) gemm_tf(
    const float* __restrict__ A, const float* __restrict__ A2,
    const float* __restrict__ W,
    const float* __restrict__ bias, float* __restrict__ C,
    float* __restrict__ Ct,
    const float* __restrict__ Wd, const float* __restrict__ biasd,
    float* __restrict__ Cd, float* __restrict__ Ctd,
    const float* __restrict__ R, const float* __restrict__ rs,
    const float* __restrict__ gam, const float* __restrict__ bet,
    int K, int ldc, int mode, int batchW, int dualY)
{
    extern __shared__ char smem[];
    float* sf = (float*)smem;
    uint32_t sb = smem_to_u32(smem);
    const int tid = threadIdx.x, lane = tid & 31, wid = tid >> 5;
    const int wm = wid >> 2, wn = wid & 3;
    const int lr = lane >> 2, lc = lane & 3;
    int by = blockIdx.y;
    const int bn = blockIdx.x * 128;

    const float* Au = A;
    if (dualY > 0 && by >= dualY) {
        by -= dualY;
        Au = A2; W = Wd; bias = biasd; C = Cd; Ct = Ctd;
    } else if (dualY == 0 && A2 && bn > 0) {
        Au = A2;
    }
    const int bm = by * 64;
    if (batchW) W += (size_t)(bm >> 11) * (size_t)batchW;

    const int nch = K >> 5;

    float acc[2][4][4];
    #pragma unroll
    for (int i = 0; i < 2; i++)
        #pragma unroll
        for (int j = 0; j < 4; j++)
            #pragma unroll
            for (int k = 0; k < 4; k++) acc[i][j][k] = 0.f;

    const int rowA = tid >> 3, qA = tid & 7;

    // prologue: chunks 0 and 1 into stages 0 and 1
    #pragma unroll
    for (int p = 0; p < 2; p++) {
        const uint32_t stg = p * GSTT;
        const int k0 = p * 32;
        #pragma unroll
        for (int j = 0; j < 2; j++) {
            int row = rowA + j * 32;
            CP16(sb + stg + row * 144 + qA * 16, Au + (size_t)(bm + row) * K + k0 + qA * 4);
        }
        #pragma unroll
        for (int j = 0; j < 4; j++) {
            int row = rowA + j * 32;
            CP16(sb + stg + 9216 + row * 144 + qA * 16, W + (size_t)(bn + row) * K + k0 + qA * 4);
        }
        CP_COMMIT();
    }

    for (int c = 0; c < nch; c++) {
        if (c + 2 < nch) { CP_WAIT(1); } else { CP_WAIT(0); }
        __syncthreads();
        if (c + 2 < nch) {
            uint32_t stg = ((c + 2) % 3) * GSTT;
            const int k0 = (c + 2) * 32;
            #pragma unroll
            for (int j = 0; j < 2; j++) {
                int row = rowA + j * 32;
                CP16(sb + stg + row * 144 + qA * 16, Au + (size_t)(bm + row) * K + k0 + qA * 4);
            }
            #pragma unroll
            for (int j = 0; j < 4; j++) {
                int row = rowA + j * 32;
                CP16(sb + stg + 9216 + row * 144 + qA * 16, W + (size_t)(bn + row) * K + k0 + qA * 4);
            }
            CP_COMMIT();
        }
        const float* tA = sf + (c % 3) * (GSTT / 4);
        const float* tB = tA + 2304;
        #pragma unroll
        for (int ks = 0; ks < 4; ks++) {
            const int ko = ks * 8;
            uint32_t af[2][4], bf[4][2];
            #pragma unroll
            for (int mt = 0; mt < 2; mt++) {
                int r0 = (wm * 32 + mt * 16 + lr) * 36 + ko + lc;
                af[mt][0] = __float_as_uint(tA[r0]);
                af[mt][1] = __float_as_uint(tA[r0 + 8 * 36]);
                af[mt][2] = __float_as_uint(tA[r0 + 4]);
                af[mt][3] = __float_as_uint(tA[r0 + 8 * 36 + 4]);
            }
            #pragma unroll
            for (int nt = 0; nt < 4; nt++) {
                int n0 = (wn * 32 + nt * 8 + lr) * 36 + ko + lc;
                bf[nt][0] = __float_as_uint(tB[n0]);
                bf[nt][1] = __float_as_uint(tB[n0 + 4]);
            }
            #pragma unroll
            for (int mt = 0; mt < 2; mt++)
                #pragma unroll
                for (int nt = 0; nt < 4; nt++)
                    MMA_TF32(acc[mt][nt], af[mt], bf[nt]);
        }
    }
    __syncthreads();

    // ---------------- epilogues ----------------
    if (mode == EP_SIMDOT) {
        float* simS = (float*)smem;
        if (tid < 64) simS[tid] = 0.f;
        __syncthreads();
        #pragma unroll
        for (int mt = 0; mt < 2; mt++) {
            int row0 = bm + wm * 32 + mt * 16 + lr;
            float d0 = 0.f, d1 = 0.f;
            #pragma unroll
            for (int nt = 0; nt < 4; nt++) {
                int col = bn + wn * 32 + nt * 8 + 2 * lc;
                float2 s0 = *(const float2*)(R + (size_t)row0 * 128 + col);
                float2 s1 = *(const float2*)(R + (size_t)(row0 + 8) * 128 + col);
                d0 += acc[mt][nt][0] * s0.x + acc[mt][nt][1] * s0.y;
                d1 += acc[mt][nt][2] * s1.x + acc[mt][nt][3] * s1.y;
            }
            d0 += __shfl_xor_sync(0xffffffffu, d0, 1);
            d0 += __shfl_xor_sync(0xffffffffu, d0, 2);
            d1 += __shfl_xor_sync(0xffffffffu, d1, 1);
            d1 += __shfl_xor_sync(0xffffffffu, d1, 2);
            if (lc == 0) {
                atomicAdd(&simS[wm * 32 + mt * 16 + lr], d0);
                atomicAdd(&simS[wm * 32 + mt * 16 + lr + 8], d1);
            }
        }
        __syncthreads();
        if (tid < 64) C[bm + tid] = simS[tid] * (1.f / 2048.f);
        return;
    }

    #pragma unroll
    for (int mt = 0; mt < 2; mt++) {
        int row = bm + wm * 32 + mt * 16 + lr;
        #pragma unroll
        for (int nt = 0; nt < 4; nt++) {
            int col = bn + wn * 32 + nt * 8 + 2 * lc;
            float2 b2 = *(const float2*)(bias + col);
            float* a = acc[mt][nt];
            a[0] += b2.x; a[1] += b2.y; a[2] += b2.x; a[3] += b2.y;
            if (mode == EP_LN || mode == EP_LN2) {
                float2 r0 = *(const float2*)(R + (size_t)row * ldc + col);
                float2 r1 = *(const float2*)(R + (size_t)(row + 8) * ldc + col);
                a[0] += r0.x; a[1] += r0.y; a[2] += r1.x; a[3] += r1.y;
            } else if (mode == EP_GELU) {
                a[0] = gelu_f(a[0]); a[1] = gelu_f(a[1]);
                a[2] = gelu_f(a[2]); a[3] = gelu_f(a[3]);
            } else if (mode == EP_FINAL) {
                float2 r0 = *(const float2*)(R + (size_t)row * ldc + col);
                float2 r1 = *(const float2*)(R + (size_t)(row + 8) * ldc + col);
                float sc0 = rs[row], sc1 = rs[row + 8];
                a[0] = r0.x + sc0 * a[0]; a[1] = r0.y + sc0 * a[1];
                a[2] = r1.x + sc1 * a[2]; a[3] = r1.y + sc1 * a[3];
            }
        }
    }

    if (mode == EP_LN || mode == EP_LN2 || mode == EP_COS) {
        float* ps = (float*)smem;        // [64][4]
        float* ps2 = ps + 256;
        #pragma unroll
        for (int mt = 0; mt < 2; mt++) {
            float p0 = 0.f, p1 = 0.f, q0 = 0.f, q1 = 0.f;
            #pragma unroll
            for (int nt = 0; nt < 4; nt++) {
                float* a = acc[mt][nt];
                p0 += a[0] + a[1]; q0 += a[0] * a[0] + a[1] * a[1];
                p1 += a[2] + a[3]; q1 += a[2] * a[2] + a[3] * a[3];
            }
            p0 += __shfl_xor_sync(0xffffffffu, p0, 1); p0 += __shfl_xor_sync(0xffffffffu, p0, 2);
            p1 += __shfl_xor_sync(0xffffffffu, p1, 1); p1 += __shfl_xor_sync(0xffffffffu, p1, 2);
            q0 += __shfl_xor_sync(0xffffffffu, q0, 1); q0 += __shfl_xor_sync(0xffffffffu, q0, 2);
            q1 += __shfl_xor_sync(0xffffffffu, q1, 1); q1 += __shfl_xor_sync(0xffffffffu, q1, 2);
            if (lc == 0) {
                int r0l = wm * 32 + mt * 16 + lr;
                ps[r0l * 4 + wn] = p0; ps2[r0l * 4 + wn] = q0;
                ps[(r0l + 8) * 4 + wn] = p1; ps2[(r0l + 8) * 4 + wn] = q1;
            }
        }
        __syncthreads();
        #pragma unroll
        for (int mt = 0; mt < 2; mt++) {
            int r0l = wm * 32 + mt * 16 + lr;
            float s0 = 0.f, t0 = 0.f, s1 = 0.f, t1 = 0.f;
            #pragma unroll
            for (int w4 = 0; w4 < 4; w4++) {
                s0 += ps[r0l * 4 + w4]; t0 += ps2[r0l * 4 + w4];
                s1 += ps[(r0l + 8) * 4 + w4]; t1 += ps2[(r0l + 8) * 4 + w4];
            }
            int row0 = bm + r0l;
            if (mode == EP_COS) {
                float i0 = 1.f / fmaxf(sqrtf(t0), 1e-8f);
                float i1 = 1.f / fmaxf(sqrtf(t1), 1e-8f);
                #pragma unroll
                for (int nt = 0; nt < 4; nt++) {
                    int col = bn + wn * 32 + nt * 8 + 2 * lc;
                    float* a = acc[mt][nt];
                    size_t i0x = (size_t)row0 * ldc + col, i1x = (size_t)(row0 + 8) * ldc + col;
                    *(float2*)(Ct + i0x) = make_float2(a[0], a[1]);   // raw embed
                    *(float2*)(Ct + i1x) = make_float2(a[2], a[3]);
                    *(float2*)(C + i0x) = make_float2(a[0] * i0, a[1] * i0);  // normalized
                    *(float2*)(C + i1x) = make_float2(a[2] * i1, a[3] * i1);
                }
            } else {
                float mu0 = s0 * (1.f / 128.f), mu1 = s1 * (1.f / 128.f);
                float rs0 = rsqrtf(t0 * (1.f / 128.f) - mu0 * mu0 + 1e-5f);
                float rs1 = rsqrtf(t1 * (1.f / 128.f) - mu1 * mu1 + 1e-5f);
                #pragma unroll
                for (int nt = 0; nt < 4; nt++) {
                    int col = bn + wn * 32 + nt * 8 + 2 * lc;
                    float* a = acc[mt][nt];
                    float2 g2 = *(const float2*)(gam + col);
                    float2 be2 = *(const float2*)(bet + col);
                    float w0 = (a[0] - mu0) * rs0 * g2.x + be2.x;
                    float w1 = (a[1] - mu0) * rs0 * g2.y + be2.y;
                    float w2 = (a[2] - mu1) * rs1 * g2.x + be2.x;
                    float w3 = (a[3] - mu1) * rs1 * g2.y + be2.y;
                    size_t i0x = (size_t)row0 * ldc + col, i1x = (size_t)(row0 + 8) * ldc + col;
                    *(float2*)(C + i0x) = make_float2(w0, w1);
                    *(float2*)(C + i1x) = make_float2(w2, w3);
                }
            }
        }
    } else {
        #pragma unroll
        for (int mt = 0; mt < 2; mt++) {
            int row = bm + wm * 32 + mt * 16 + lr;
            #pragma unroll
            for (int nt = 0; nt < 4; nt++) {
                int col = bn + wn * 32 + nt * 8 + 2 * lc;
                float* a = acc[mt][nt];
                size_t i0x = (size_t)row * ldc + col, i1x = (size_t)(row + 8) * ldc + col;
                *(float2*)(C + i0x) = make_float2(a[0], a[1]);
                *(float2*)(C + i1x) = make_float2(a[2], a[3]);
            }
        }
    }
}

// ============== M covariance: M[b] += sn^T tn (contract over s) ==============
// Tiles stored [s][d]: 32 rows x 132 floats (528B stride). 3-stage pipeline.
#define CSTT 33792
__global__ void __launch_bounds__(256, 2) mcov_tf(
    const float* __restrict__ sn, const float* __restrict__ tn, float* __restrict__ M)
{
    extern __shared__ char smem[];
    float* sf = (float*)smem;
    uint32_t sb = smem_to_u32(smem);
    const int tid = threadIdx.x, lane = tid & 31, wid = tid >> 5;
    const int wm = wid >> 2, wn = wid & 3;
    const int lr = lane >> 2, lc = lane & 3;
    const int b = blockIdx.y, split = blockIdx.x;
    const size_t srow0 = (size_t)b * SS + split * 128;

    float acc[4][4][4];
    #pragma unroll
    for (int i = 0; i < 4; i++)
        #pragma unroll
        for (int j = 0; j < 4; j++)
            #pragma unroll
            for (int k = 0; k < 4; k++) acc[i][j][k] = 0.f;

    const int rowL = tid >> 5, qL = tid & 31;
    #pragma unroll
    for (int p = 0; p < 2; p++) {
        const uint32_t stg = p * CSTT;
        const size_t so = srow0 + (size_t)p * 32;
        #pragma unroll
        for (int j = 0; j < 4; j++) {
            int row = rowL + j * 8;
            CP16(sb + stg + row * 528 + qL * 16, sn + (so + row) * 128 + qL * 4);
            CP16(sb + stg + 16896 + row * 528 + qL * 16, tn + (so + row) * 128 + qL * 4);
        }
        CP_COMMIT();
    }

    for (int c = 0; c < 4; c++) {
        if (c + 2 < 4) { CP_WAIT(1); } else { CP_WAIT(0); }
        __syncthreads();
        if (c + 2 < 4) {
            uint32_t stg = ((c + 2) % 3) * CSTT;
            const size_t so = srow0 + (size_t)(c + 2) * 32;
            #pragma unroll
            for (int j = 0; j < 4; j++) {
                int row = rowL + j * 8;
                CP16(sb + stg + row * 528 + qL * 16, sn + (so + row) * 128 + qL * 4);
                CP16(sb + stg + 16896 + row * 528 + qL * 16, tn + (so + row) * 128 + qL * 4);
            }
            CP_COMMIT();
        }
        const float* tS = sf + (c % 3) * (CSTT / 4);
        const float* tT = tS + 4224;
        #pragma unroll
        for (int ks = 0; ks < 4; ks++) {
            const int ko = ks * 8;
            uint32_t af[4][4], bf[4][2];
            #pragma unroll
            for (int mt = 0; mt < 4; mt++) {
                int d0 = wm * 64 + mt * 16 + lr;
                af[mt][0] = __float_as_uint(tS[(ko + lc) * 132 + d0]);
                af[mt][1] = __float_as_uint(tS[(ko + lc) * 132 + d0 + 8]);
                af[mt][2] = __float_as_uint(tS[(ko + lc + 4) * 132 + d0]);
                af[mt][3] = __float_as_uint(tS[(ko + lc + 4) * 132 + d0 + 8]);
            }
            #pragma unroll
            for (int nt = 0; nt < 4; nt++) {
                int e0 = wn * 32 + nt * 8 + lr;
                bf[nt][0] = __float_as_uint(tT[(ko + lc) * 132 + e0]);
                bf[nt][1] = __float_as_uint(tT[(ko + lc + 4) * 132 + e0]);
            }
            #pragma unroll
            for (int mt = 0; mt < 4; mt++)
                #pragma unroll
                for (int nt = 0; nt < 4; nt++)
                    MMA_TF32(acc[mt][nt], af[mt], bf[nt]);
        }
    }

    float* Mb = M + (size_t)b * 16384;
    #pragma unroll
    for (int mt = 0; mt < 4; mt++) {
        int row = wm * 64 + mt * 16 + lr;
        #pragma unroll
        for (int nt = 0; nt < 4; nt++) {
            int col = wn * 32 + nt * 8 + 2 * lc;
            atomicAdd(&Mb[(size_t)row * 128 + col], acc[mt][nt][0]);
            atomicAdd(&Mb[(size_t)row * 128 + col + 1], acc[mt][nt][1]);
            atomicAdd(&Mb[(size_t)(row + 8) * 128 + col], acc[mt][nt][2]);
            atomicAdd(&Mb[(size_t)(row + 8) * 128 + col + 1], acc[mt][nt][3]);
        }
    }
}

// ---------------- local windowed causal attention ----------------
__global__ __launch_bounds__(64) void lw_attn_k(const float* __restrict__ qkv,
                                                float* __restrict__ outp)
{
    int g = blockIdx.x, h = blockIdx.y, i = threadIdx.x;
    __shared__ float ks[64][17];
    __shared__ float vs[64][17];
    size_t tbase = (size_t)g * 64;
    const float* kp = qkv + (tbase + i) * 384 + 128 + h * 16;
    const float* vp = kp + 128;
    #pragma unroll
    for (int d = 0; d < 16; d++) { ks[i][d] = kp[d]; vs[i][d] = vp[d]; }
    float q[16];
    const float* qp = qkv + (tbase + i) * 384 + h * 16;
    #pragma unroll
    for (int d = 0; d < 16; d++) q[d] = qp[d];
    __syncthreads();
    float sc[64];
    float mx = -1e30f;
    #pragma unroll
    for (int j = 0; j < 64; j++) {
        float dv = 0.f;
        #pragma unroll
        for (int d = 0; d < 16; d++) dv += q[d] * ks[j][d];
        sc[j] = (j <= i) ? dv * 0.25f : -INFINITY;
        mx = fmaxf(mx, sc[j]);
    }
    float sum = 0.f;
    #pragma unroll
    for (int j = 0; j < 64; j++) { float e = expf(sc[j] - mx); sc[j] = e; sum += e; }
    float o[16] = {};
    #pragma unroll
    for (int j = 0; j < 64; j++) {
        float w = sc[j];
        #pragma unroll
        for (int d = 0; d < 16; d++) o[d] += w * vs[j][d];
    }
    float inv = 1.f / sum;
    float* op = outp + (tbase + i) * 128 + h * 16;
    #pragma unroll
    for (int d = 0; d < 16; d++) op[d] = o[d] * inv;
}

// ---------------- interaction MHA (len = B = 8) ----------------
__global__ __launch_bounds__(64) void int_attn_k(const float* __restrict__ qkv,
                                                 float* __restrict__ outp)
{
    int s = blockIdx.x, tid = threadIdx.x;
    __shared__ float kvs[8][256];
    for (int idx = tid; idx < 8 * 256; idx += 64) {
        int jb = idx >> 8, c = idx & 255;
        kvs[jb][c] = qkv[((size_t)jb * SS + s) * 384 + 128 + c];
    }
    __syncthreads();
    int h = tid >> 3, qb = tid & 7;
    float q[16];
    const float* qp = qkv + ((size_t)qb * SS + s) * 384 + h * 16;
    #pragma unroll
    for (int d = 0; d < 16; d++) q[d] = qp[d];
    float sc[8];
    float mx = -1e30f;
    #pragma unroll
    for (int jb = 0; jb < 8; jb++) {
        float dv = 0.f;
        #pragma unroll
        for (int d = 0; d < 16; d++) dv += q[d] * kvs[jb][h * 16 + d];
        sc[jb] = dv * 0.25f;
        mx = fmaxf(mx, sc[jb]);
    }
    float sum = 0.f;
    #pragma unroll
    for (int jb = 0; jb < 8; jb++) { float e = expf(sc[jb] - mx); sc[jb] = e; sum += e; }
    float o[16] = {};
    #pragma unroll
    for (int jb = 0; jb < 8; jb++) {
        float w = sc[jb];
        #pragma unroll
        for (int d = 0; d < 16; d++) o[d] += w * kvs[jb][128 + h * 16 + d];
    }
    float inv = 1.f / sum;
    float* op = outp + ((size_t)qb * SS + s) * 128 + h * 16;
    #pragma unroll
    for (int d = 0; d < 16; d++) op[d] = o[d] * inv;
}

extern "C" void kernel_launch(void* const* d_in, const int* in_sizes, int n_in,
                              void* d_out, int out_size)
{
    const float* x        = (const float*)d_in[0];
    const float* sp       = (const float*)d_in[1];
    const float* tp       = (const float*)d_in[2];
    const float* lw_in_w  = (const float*)d_in[3];
    const float* lw_in_b  = (const float*)d_in[4];
    const float* lw_out_w = (const float*)d_in[5];
    const float* lw_out_b = (const float*)d_in[6];
    const float* spat_w   = (const float*)d_in[7];
    const float* spat_b   = (const float*)d_in[8];
    const float* temp_w   = (const float*)d_in[9];
    const float* temp_b   = (const float*)d_in[10];
    const float* int_in_w = (const float*)d_in[11];
    const float* int_in_b = (const float*)d_in[12];
    const float* int_out_w= (const float*)d_in[13];
    const float* int_out_b= (const float*)d_in[14];
    const float* ffn_w1   = (const float*)d_in[15];
    const float* ffn_b1   = (const float*)d_in[16];
    const float* ffn_w2   = (const float*)d_in[17];
    const float* ffn_b2   = (const float*)d_in[18];
    const float* ln1_g    = (const float*)d_in[19];
    const float* ln1_b    = (const float*)d_in[20];
    const float* ln2_g    = (const float*)d_in[21];
    const float* ln2_b    = (const float*)d_in[22];
    float* out = (float*)d_out;

    float* f32 = nullptr;
    cudaGetSymbolAddress((void**)&f32, g_f32);

    static cudaStream_t s2 = nullptr;
    static cudaEvent_t evF = nullptr, evJ = nullptr;
    static bool init_done = false;
    if (!init_done) {
        cudaFuncSetAttribute(gemm_tf, cudaFuncAttributeMaxDynamicSharedMemorySize, 3 * GSTT);
        cudaFuncSetAttribute(mcov_tf, cudaFuncAttributeMaxDynamicSharedMemorySize, 3 * CSTT);
        cudaStreamCreateWithFlags(&s2, cudaStreamNonBlocking);
        cudaEventCreateWithFlags(&evF, cudaEventDisableTiming);
        cudaEventCreateWithFlags(&evJ, cudaEventDisableTiming);
        init_done = true;
    }

    float* qkv   = f32 + F_QKV;
    float* qkv2  = f32 + F_QKV2;
    float* att   = f32 + F_ATT;
    float* att2  = f32 + F_ATT2;
    float* bufb  = f32 + F_BUFB;
    float* bufh  = f32 + F_BUFH;
    float* bufc  = f32 + F_BUFC;
    float* se    = f32 + F_SE;
    float* sn    = f32 + F_SN;
    float* te    = f32 + F_TE;
    float* tn    = f32 + F_TN;
    float* bM    = f32 + F_M;
    float* bsim  = f32 + F_SIM;

    #define NP4 nullptr, nullptr, nullptr, nullptr

    // ---- fork ----
    cudaEventRecord(evF, 0);
    cudaStreamWaitEvent(s2, evF, 0);

    // ===== main stream: x-chain =====
    gemm_tf<<<dim3(3, 256), 256, 3 * GSTT>>>(
        x, nullptr, lw_in_w, lw_in_b, qkv, nullptr, NP4,
        nullptr, nullptr, nullptr, nullptr, 128, 384, EP_F32, 0, 0);
    lw_attn_k<<<dim3(256, 8), 64>>>(qkv, att);
    gemm_tf<<<dim3(1, 256), 256, 3 * GSTT>>>(
        att, nullptr, lw_out_w, lw_out_b, bufb, nullptr, NP4,
        x, nullptr, ln1_g, ln1_b, 128, 128, EP_LN, 0, 0);
    gemm_tf<<<dim3(4, 256), 256, 3 * GSTT>>>(
        bufb, nullptr, ffn_w1, ffn_b1, bufh, nullptr, NP4,
        nullptr, nullptr, nullptr, nullptr, 128, 512, EP_GELU, 0, 0);
    gemm_tf<<<dim3(1, 256), 256, 3 * GSTT>>>(
        bufh, nullptr, ffn_w2, ffn_b2, bufc, nullptr, NP4,
        bufb, nullptr, ln2_g, ln2_b, 512, 128, EP_LN2, 0, 0);

    // ===== stream 2: spatio-temporal chain =====
    zero_k<<<512, 256, 0, s2>>>(bM, 8 * 128 * 128);
    gemm_tf<<<dim3(1, 512), 256, 3 * GSTT, s2>>>(
        sp, tp, spat_w, spat_b, sn, se,
        temp_w, temp_b, tn, te,
        nullptr, nullptr, nullptr, nullptr, 128, 128, EP_COS, 0, 256);
    mcov_tf<<<dim3(16, 8), 256, 3 * CSTT, s2>>>(sn, tn, bM);
    gemm_tf<<<dim3(1, 256), 256, 3 * GSTT, s2>>>(
        tn, nullptr, bM, nullptr, bsim, nullptr, NP4,
        sn, nullptr, nullptr, nullptr, 128, 0, EP_SIMDOT, 16384, 0);
    gemm_tf<<<dim3(3, 256), 256, 3 * GSTT, s2>>>(
        se, te, int_in_w, int_in_b, qkv2, nullptr, NP4,
        nullptr, nullptr, nullptr, nullptr, 128, 384, EP_F32, 0, 0);
    int_attn_k<<<SS, 64, 0, s2>>>(qkv2, att2);
    cudaEventRecord(evJ, s2);

    // ---- join + final ----
    cudaStreamWaitEvent(0, evJ, 0);
    gemm_tf<<<dim3(1, 256), 256, 3 * GSTT>>>(
        att2, nullptr, int_out_w, int_out_b, out, nullptr, NP4,
        bufc, bsim, nullptr, nullptr, 128, 128, EP_FINAL, 0, 0);
}

// round 14
// speedup vs baseline: 1.0128x; 1.0128x over previous
#include <cuda_runtime.h>
#include <cstdint>
#include <math.h>

#define BB 8
#define SS 2048
#define TT 16384

// ---------------- fp32 scratch ----------------
#define F_QKV  0u            // 16384*384
#define F_QKV2 6291456u      // 16384*384
#define F_ATT  12582912u     // 16384*128
#define F_ATT2 14680064u
#define F_BUFB 16777216u
#define F_BUFH 18874368u     // 16384*512
#define F_BUFC 27262976u
#define F_SE   29360128u
#define F_SN   31457280u
#define F_TE   33554432u
#define F_TN   35651584u
#define F_M    37748736u     // 8*128*128
#define F_SIM  37879808u     // 16384
#define F_TOT  37896192u
__device__ float g_f32[F_TOT];

enum { EP_F32 = 0, EP_LN = 1, EP_GELU = 2, EP_LN2 = 3, EP_COS = 4, EP_FINAL = 5, EP_SIMDOT = 6 };

__device__ __forceinline__ uint32_t smem_to_u32(const void* p) {
    uint32_t a;
    asm("{ .reg .u64 t; cvta.to.shared.u64 t, %1; cvt.u32.u64 %0, t; }" : "=r"(a) : "l"(p));
    return a;
}

#define CP16(dst, src) do { \
    unsigned long long _gs = (unsigned long long)__cvta_generic_to_global((const void*)(src)); \
    asm volatile("cp.async.cg.shared.global [%0], [%1], 16;" :: "r"(dst), "l"(_gs)); } while (0)
#define CP_COMMIT() asm volatile("cp.async.commit_group;" ::: "memory")
#define CP_WAIT(n) asm volatile("cp.async.wait_group %0;" :: "n"(n) : "memory")

// tf32 mma: D(16x8) += A(16x8) * B(8x8); raw f32 regs truncated to tf32 by HW
#define MMA_TF32(c, a, b) \
    asm volatile("mma.sync.aligned.m16n8k8.row.col.f32.tf32.tf32.f32 " \
        "{%0,%1,%2,%3}, {%4,%5,%6,%7}, {%8,%9}, {%0,%1,%2,%3};" \
        : "+f"((c)[0]), "+f"((c)[1]), "+f"((c)[2]), "+f"((c)[3]) \
        : "r"((a)[0]), "r"((a)[1]), "r"((a)[2]), "r"((a)[3]), "r"((b)[0]), "r"((b)[1]))

__device__ __forceinline__ float gelu_f(float v) {
    return 0.5f * v * (1.0f + erff(v * 0.70710678118654752f));
}

__global__ void zero_k(float* p, int n)
{
    int i = blockIdx.x * 256 + threadIdx.x;
    if (i < n) p[i] = 0.f;
}

// ============== generic tf32 GEMM: C[M,N] = A @ W^T ==============
// Tile 64(M) x 128(N), 256 threads = 8 warps (2 wm x 4 wn), warp tile 32x32.
// smem stage (27648B): A +0 (64 rows x 36 floats), B +9216 (128 rows x 36 floats).
// 2-stage single-sync pipeline. Dual-problem mode optional (dualY>0).
#define GSTT 27648
__global__ void __launch_bounds__(256, 3) gemm_tf(
    const float* __restrict__ A, const float* __restrict__ A2,
    const float* __restrict__ W,
    const float* __restrict__ bias, float* __restrict__ C,
    float* __restrict__ Ct,
    const float* __restrict__ Wd, const float* __restrict__ biasd,
    float* __restrict__ Cd, float* __restrict__ Ctd,
    const float* __restrict__ R, const float* __restrict__ rs,
    const float* __restrict__ gam, const float* __restrict__ bet,
    int K, int ldc, int mode, int batchW, int dualY)
{
    extern __shared__ char smem[];
    float* sf = (float*)smem;
    uint32_t sb = smem_to_u32(smem);
    const int tid = threadIdx.x, lane = tid & 31, wid = tid >> 5;
    const int wm = wid >> 2, wn = wid & 3;
    const int lr = lane >> 2, lc = lane & 3;
    int by = blockIdx.y;
    const int bn = blockIdx.x * 128;

    const float* Au = A;
    if (dualY > 0 && by >= dualY) {
        by -= dualY;
        Au = A2; W = Wd; bias = biasd; C = Cd; Ct = Ctd;
    } else if (dualY == 0 && A2 && bn > 0) {
        Au = A2;
    }
    const int bm = by * 64;
    if (batchW) W += (size_t)(bm >> 11) * (size_t)batchW;

    const int nch = K >> 5;

    float acc[2][4][4];
    #pragma unroll
    for (int i = 0; i < 2; i++)
        #pragma unroll
        for (int j = 0; j < 4; j++)
            #pragma unroll
            for (int k = 0; k < 4; k++) acc[i][j][k] = 0.f;

    const int rowA = tid >> 3, qA = tid & 7;
    // prologue: chunk 0 -> stage 0
    #pragma unroll
    for (int j = 0; j < 2; j++) {
        int row = rowA + j * 32;
        CP16(sb + row * 144 + qA * 16, Au + (size_t)(bm + row) * K + qA * 4);
    }
    #pragma unroll
    for (int j = 0; j < 4; j++) {
        int row = rowA + j * 32;
        CP16(sb + 9216 + row * 144 + qA * 16, W + (size_t)(bn + row) * K + qA * 4);
    }
    CP_COMMIT();

    for (int c = 0; c < nch; c++) {
        CP_WAIT(0);
        __syncthreads();
        if (c + 1 < nch) {
            uint32_t stg = ((c + 1) & 1) * GSTT;
            const int k0 = (c + 1) * 32;
            #pragma unroll
            for (int j = 0; j < 2; j++) {
                int row = rowA + j * 32;
                CP16(sb + stg + row * 144 + qA * 16, Au + (size_t)(bm + row) * K + k0 + qA * 4);
            }
            #pragma unroll
            for (int j = 0; j < 4; j++) {
                int row = rowA + j * 32;
                CP16(sb + stg + 9216 + row * 144 + qA * 16, W + (size_t)(bn + row) * K + k0 + qA * 4);
            }
            CP_COMMIT();
        }
        const float* tA = sf + (c & 1) * (GSTT / 4);
        const float* tB = tA + 2304;
        #pragma unroll
        for (int ks = 0; ks < 4; ks++) {
            const int ko = ks * 8;
            uint32_t af[2][4], bf[4][2];
            #pragma unroll
            for (int mt = 0; mt < 2; mt++) {
                int r0 = (wm * 32 + mt * 16 + lr) * 36 + ko + lc;
                af[mt][0] = __float_as_uint(tA[r0]);
                af[mt][1] = __float_as_uint(tA[r0 + 8 * 36]);
                af[mt][2] = __float_as_uint(tA[r0 + 4]);
                af[mt][3] = __float_as_uint(tA[r0 + 8 * 36 + 4]);
            }
            #pragma unroll
            for (int nt = 0; nt < 4; nt++) {
                int n0 = (wn * 32 + nt * 8 + lr) * 36 + ko + lc;
                bf[nt][0] = __float_as_uint(tB[n0]);
                bf[nt][1] = __float_as_uint(tB[n0 + 4]);
            }
            #pragma unroll
            for (int mt = 0; mt < 2; mt++)
                #pragma unroll
                for (int nt = 0; nt < 4; nt++)
                    MMA_TF32(acc[mt][nt], af[mt], bf[nt]);
        }
    }
    __syncthreads();

    // ---------------- epilogues ----------------
    if (mode == EP_SIMDOT) {
        float* simS = (float*)smem;
        if (tid < 64) simS[tid] = 0.f;
        __syncthreads();
        #pragma unroll
        for (int mt = 0; mt < 2; mt++) {
            int row0 = bm + wm * 32 + mt * 16 + lr;
            float d0 = 0.f, d1 = 0.f;
            #pragma unroll
            for (int nt = 0; nt < 4; nt++) {
                int col = bn + wn * 32 + nt * 8 + 2 * lc;
                float2 s0 = *(const float2*)(R + (size_t)row0 * 128 + col);
                float2 s1 = *(const float2*)(R + (size_t)(row0 + 8) * 128 + col);
                d0 += acc[mt][nt][0] * s0.x + acc[mt][nt][1] * s0.y;
                d1 += acc[mt][nt][2] * s1.x + acc[mt][nt][3] * s1.y;
            }
            d0 += __shfl_xor_sync(0xffffffffu, d0, 1);
            d0 += __shfl_xor_sync(0xffffffffu, d0, 2);
            d1 += __shfl_xor_sync(0xffffffffu, d1, 1);
            d1 += __shfl_xor_sync(0xffffffffu, d1, 2);
            if (lc == 0) {
                atomicAdd(&simS[wm * 32 + mt * 16 + lr], d0);
                atomicAdd(&simS[wm * 32 + mt * 16 + lr + 8], d1);
            }
        }
        __syncthreads();
        if (tid < 64) C[bm + tid] = simS[tid] * (1.f / 2048.f);
        return;
    }

    #pragma unroll
    for (int mt = 0; mt < 2; mt++) {
        int row = bm + wm * 32 + mt * 16 + lr;
        #pragma unroll
        for (int nt = 0; nt < 4; nt++) {
            int col = bn + wn * 32 + nt * 8 + 2 * lc;
            float2 b2 = *(const float2*)(bias + col);
            float* a = acc[mt][nt];
            a[0] += b2.x; a[1] += b2.y; a[2] += b2.x; a[3] += b2.y;
            if (mode == EP_LN || mode == EP_LN2) {
                float2 r0 = *(const float2*)(R + (size_t)row * ldc + col);
                float2 r1 = *(const float2*)(R + (size_t)(row + 8) * ldc + col);
                a[0] += r0.x; a[1] += r0.y; a[2] += r1.x; a[3] += r1.y;
            } else if (mode == EP_GELU) {
                a[0] = gelu_f(a[0]); a[1] = gelu_f(a[1]);
                a[2] = gelu_f(a[2]); a[3] = gelu_f(a[3]);
            } else if (mode == EP_FINAL) {
                float2 r0 = *(const float2*)(R + (size_t)row * ldc + col);
                float2 r1 = *(const float2*)(R + (size_t)(row + 8) * ldc + col);
                float sc0 = rs[row], sc1 = rs[row + 8];
                a[0] = r0.x + sc0 * a[0]; a[1] = r0.y + sc0 * a[1];
                a[2] = r1.x + sc1 * a[2]; a[3] = r1.y + sc1 * a[3];
            }
        }
    }

    if (mode == EP_LN || mode == EP_LN2 || mode == EP_COS) {
        float* ps = (float*)smem;        // [64][4]
        float* ps2 = ps + 256;
        #pragma unroll
        for (int mt = 0; mt < 2; mt++) {
            float p0 = 0.f, p1 = 0.f, q0 = 0.f, q1 = 0.f;
            #pragma unroll
            for (int nt = 0; nt < 4; nt++) {
                float* a = acc[mt][nt];
                p0 += a[0] + a[1]; q0 += a[0] * a[0] + a[1] * a[1];
                p1 += a[2] + a[3]; q1 += a[2] * a[2] + a[3] * a[3];
            }
            p0 += __shfl_xor_sync(0xffffffffu, p0, 1); p0 += __shfl_xor_sync(0xffffffffu, p0, 2);
            p1 += __shfl_xor_sync(0xffffffffu, p1, 1); p1 += __shfl_xor_sync(0xffffffffu, p1, 2);
            q0 += __shfl_xor_sync(0xffffffffu, q0, 1); q0 += __shfl_xor_sync(0xffffffffu, q0, 2);
            q1 += __shfl_xor_sync(0xffffffffu, q1, 1); q1 += __shfl_xor_sync(0xffffffffu, q1, 2);
            if (lc == 0) {
                int r0l = wm * 32 + mt * 16 + lr;
                ps[r0l * 4 + wn] = p0; ps2[r0l * 4 + wn] = q0;
                ps[(r0l + 8) * 4 + wn] = p1; ps2[(r0l + 8) * 4 + wn] = q1;
            }
        }
        __syncthreads();
        #pragma unroll
        for (int mt = 0; mt < 2; mt++) {
            int r0l = wm * 32 + mt * 16 + lr;
            float s0 = 0.f, t0 = 0.f, s1 = 0.f, t1 = 0.f;
            #pragma unroll
            for (int w4 = 0; w4 < 4; w4++) {
                s0 += ps[r0l * 4 + w4]; t0 += ps2[r0l * 4 + w4];
                s1 += ps[(r0l + 8) * 4 + w4]; t1 += ps2[(r0l + 8) * 4 + w4];
            }
            int row0 = bm + r0l;
            if (mode == EP_COS) {
                float i0 = 1.f / fmaxf(sqrtf(t0), 1e-8f);
                float i1 = 1.f / fmaxf(sqrtf(t1), 1e-8f);
                #pragma unroll
                for (int nt = 0; nt < 4; nt++) {
                    int col = bn + wn * 32 + nt * 8 + 2 * lc;
                    float* a = acc[mt][nt];
                    size_t i0x = (size_t)row0 * ldc + col, i1x = (size_t)(row0 + 8) * ldc + col;
                    *(float2*)(Ct + i0x) = make_float2(a[0], a[1]);   // raw embed
                    *(float2*)(Ct + i1x) = make_float2(a[2], a[3]);
                    *(float2*)(C + i0x) = make_float2(a[0] * i0, a[1] * i0);  // normalized
                    *(float2*)(C + i1x) = make_float2(a[2] * i1, a[3] * i1);
                }
            } else {
                float mu0 = s0 * (1.f / 128.f), mu1 = s1 * (1.f / 128.f);
                float rs0 = rsqrtf(t0 * (1.f / 128.f) - mu0 * mu0 + 1e-5f);
                float rs1 = rsqrtf(t1 * (1.f / 128.f) - mu1 * mu1 + 1e-5f);
                #pragma unroll
                for (int nt = 0; nt < 4; nt++) {
                    int col = bn + wn * 32 + nt * 8 + 2 * lc;
                    float* a = acc[mt][nt];
                    float2 g2 = *(const float2*)(gam + col);
                    float2 be2 = *(const float2*)(bet + col);
                    float w0 = (a[0] - mu0) * rs0 * g2.x + be2.x;
                    float w1 = (a[1] - mu0) * rs0 * g2.y + be2.y;
                    float w2 = (a[2] - mu1) * rs1 * g2.x + be2.x;
                    float w3 = (a[3] - mu1) * rs1 * g2.y + be2.y;
                    size_t i0x = (size_t)row0 * ldc + col, i1x = (size_t)(row0 + 8) * ldc + col;
                    *(float2*)(C + i0x) = make_float2(w0, w1);
                    *(float2*)(C + i1x) = make_float2(w2, w3);
                }
            }
        }
    } else {
        #pragma unroll
        for (int mt = 0; mt < 2; mt++) {
            int row = bm + wm * 32 + mt * 16 + lr;
            #pragma unroll
            for (int nt = 0; nt < 4; nt++) {
                int col = bn + wn * 32 + nt * 8 + 2 * lc;
                float* a = acc[mt][nt];
                size_t i0x = (size_t)row * ldc + col, i1x = (size_t)(row + 8) * ldc + col;
                *(float2*)(C + i0x) = make_float2(a[0], a[1]);
                *(float2*)(C + i1x) = make_float2(a[2], a[3]);
            }
        }
    }
}

// ============== M covariance: M[b] += sn^T tn (contract over s) ==============
// Tiles stored [s][d]: 32 rows x 132 floats (528B stride). 2-stage single-sync.
#define CSTT 33792
__global__ void __launch_bounds__(256, 2) mcov_tf(
    const float* __restrict__ sn, const float* __restrict__ tn, float* __restrict__ M)
{
    extern __shared__ char smem[];
    float* sf = (float*)smem;
    uint32_t sb = smem_to_u32(smem);
    const int tid = threadIdx.x, lane = tid & 31, wid = tid >> 5;
    const int wm = wid >> 2, wn = wid & 3;
    const int lr = lane >> 2, lc = lane & 3;
    const int b = blockIdx.y, split = blockIdx.x;
    const size_t srow0 = (size_t)b * SS + split * 128;

    float acc[4][4][4];
    #pragma unroll
    for (int i = 0; i < 4; i++)
        #pragma unroll
        for (int j = 0; j < 4; j++)
            #pragma unroll
            for (int k = 0; k < 4; k++) acc[i][j][k] = 0.f;

    const int rowL = tid >> 5, qL = tid & 31;
    #pragma unroll
    for (int j = 0; j < 4; j++) {
        int row = rowL + j * 8;
        CP16(sb + row * 528 + qL * 16, sn + (srow0 + row) * 128 + qL * 4);
        CP16(sb + 16896 + row * 528 + qL * 16, tn + (srow0 + row) * 128 + qL * 4);
    }
    CP_COMMIT();

    for (int c = 0; c < 4; c++) {
        CP_WAIT(0);
        __syncthreads();
        if (c + 1 < 4) {
            uint32_t stg = ((c + 1) & 1) * CSTT;
            const size_t so = srow0 + (size_t)(c + 1) * 32;
            #pragma unroll
            for (int j = 0; j < 4; j++) {
                int row = rowL + j * 8;
                CP16(sb + stg + row * 528 + qL * 16, sn + (so + row) * 128 + qL * 4);
                CP16(sb + stg + 16896 + row * 528 + qL * 16, tn + (so + row) * 128 + qL * 4);
            }
            CP_COMMIT();
        }
        const float* tS = sf + (c & 1) * (CSTT / 4);
        const float* tT = tS + 4224;
        #pragma unroll
        for (int ks = 0; ks < 4; ks++) {
            const int ko = ks * 8;
            uint32_t af[4][4], bf[4][2];
            #pragma unroll
            for (int mt = 0; mt < 4; mt++) {
                int d0 = wm * 64 + mt * 16 + lr;
                af[mt][0] = __float_as_uint(tS[(ko + lc) * 132 + d0]);
                af[mt][1] = __float_as_uint(tS[(ko + lc) * 132 + d0 + 8]);
                af[mt][2] = __float_as_uint(tS[(ko + lc + 4) * 132 + d0]);
                af[mt][3] = __float_as_uint(tS[(ko + lc + 4) * 132 + d0 + 8]);
            }
            #pragma unroll
            for (int nt = 0; nt < 4; nt++) {
                int e0 = wn * 32 + nt * 8 + lr;
                bf[nt][0] = __float_as_uint(tT[(ko + lc) * 132 + e0]);
                bf[nt][1] = __float_as_uint(tT[(ko + lc + 4) * 132 + e0]);
            }
            #pragma unroll
            for (int mt = 0; mt < 4; mt++)
                #pragma unroll
                for (int nt = 0; nt < 4; nt++)
                    MMA_TF32(acc[mt][nt], af[mt], bf[nt]);
        }
    }

    float* Mb = M + (size_t)b * 16384;
    #pragma unroll
    for (int mt = 0; mt < 4; mt++) {
        int row = wm * 64 + mt * 16 + lr;
        #pragma unroll
        for (int nt = 0; nt < 4; nt++) {
            int col = wn * 32 + nt * 8 + 2 * lc;
            atomicAdd(&Mb[(size_t)row * 128 + col], acc[mt][nt][0]);
            atomicAdd(&Mb[(size_t)row * 128 + col + 1], acc[mt][nt][1]);
            atomicAdd(&Mb[(size_t)(row + 8) * 128 + col], acc[mt][nt][2]);
            atomicAdd(&Mb[(size_t)(row + 8) * 128 + col + 1], acc[mt][nt][3]);
        }
    }
}

// ---------------- local windowed causal attention (4 windows / 256-thr block) ----------------
__global__ __launch_bounds__(256) void lw_attn_k(const float* __restrict__ qkv,
                                                 float* __restrict__ outp)
{
    int wloc = threadIdx.x >> 6;           // window within block (0..3)
    int i = threadIdx.x & 63;              // query row
    int g = blockIdx.x * 4 + wloc;
    int h = blockIdx.y;
    __shared__ float ks[4][64][17];
    __shared__ float vs[4][64][17];
    size_t tbase = (size_t)g * 64;
    const float* kp = qkv + (tbase + i) * 384 + 128 + h * 16;
    const float* vp = kp + 128;
    #pragma unroll
    for (int d = 0; d < 16; d++) { ks[wloc][i][d] = kp[d]; vs[wloc][i][d] = vp[d]; }
    float q[16];
    const float* qp = qkv + (tbase + i) * 384 + h * 16;
    #pragma unroll
    for (int d = 0; d < 16; d++) q[d] = qp[d];
    __syncthreads();
    float sc[64];
    float mx = -1e30f;
    #pragma unroll
    for (int j = 0; j < 64; j++) {
        float dv = 0.f;
        #pragma unroll
        for (int d = 0; d < 16; d++) dv += q[d] * ks[wloc][j][d];
        sc[j] = (j <= i) ? dv * 0.25f : -INFINITY;
        mx = fmaxf(mx, sc[j]);
    }
    float sum = 0.f;
    #pragma unroll
    for (int j = 0; j < 64; j++) { float e = expf(sc[j] - mx); sc[j] = e; sum += e; }
    float o[16] = {};
    #pragma unroll
    for (int j = 0; j < 64; j++) {
        float w = sc[j];
        #pragma unroll
        for (int d = 0; d < 16; d++) o[d] += w * vs[wloc][j][d];
    }
    float inv = 1.f / sum;
    float* op = outp + (tbase + i) * 128 + h * 16;
    #pragma unroll
    for (int d = 0; d < 16; d++) op[d] = o[d] * inv;
}

// ---------------- interaction MHA (len = B = 8), 4 positions / 256-thr block ----------------
__global__ __launch_bounds__(256) void int_attn_k(const float* __restrict__ qkv,
                                                  float* __restrict__ outp)
{
    int sloc = threadIdx.x >> 6;           // position within block
    int tid = threadIdx.x & 63;
    int s = blockIdx.x * 4 + sloc;
    __shared__ float kvs[4][8][256];
    for (int idx = tid; idx < 8 * 256; idx += 64) {
        int jb = idx >> 8, c = idx & 255;
        kvs[sloc][jb][c] = qkv[((size_t)jb * SS + s) * 384 + 128 + c];
    }
    __syncthreads();
    int h = tid >> 3, qb = tid & 7;
    float q[16];
    const float* qp = qkv + ((size_t)qb * SS + s) * 384 + h * 16;
    #pragma unroll
    for (int d = 0; d < 16; d++) q[d] = qp[d];
    float sc[8];
    float mx = -1e30f;
    #pragma unroll
    for (int jb = 0; jb < 8; jb++) {
        float dv = 0.f;
        #pragma unroll
        for (int d = 0; d < 16; d++) dv += q[d] * kvs[sloc][jb][h * 16 + d];
        sc[jb] = dv * 0.25f;
        mx = fmaxf(mx, sc[jb]);
    }
    float sum = 0.f;
    #pragma unroll
    for (int jb = 0; jb < 8; jb++) { float e = expf(sc[jb] - mx); sc[jb] = e; sum += e; }
    float o[16] = {};
    #pragma unroll
    for (int jb = 0; jb < 8; jb++) {
        float w = sc[jb];
        #pragma unroll
        for (int d = 0; d < 16; d++) o[d] += w * kvs[sloc][jb][128 + h * 16 + d];
    }
    float inv = 1.f / sum;
    float* op = outp + ((size_t)qb * SS + s) * 128 + h * 16;
    #pragma unroll
    for (int d = 0; d < 16; d++) op[d] = o[d] * inv;
}

extern "C" void kernel_launch(void* const* d_in, const int* in_sizes, int n_in,
                              void* d_out, int out_size)
{
    const float* x        = (const float*)d_in[0];
    const float* sp       = (const float*)d_in[1];
    const float* tp       = (const float*)d_in[2];
    const float* lw_in_w  = (const float*)d_in[3];
    const float* lw_in_b  = (const float*)d_in[4];
    const float* lw_out_w = (const float*)d_in[5];
    const float* lw_out_b = (const float*)d_in[6];
    const float* spat_w   = (const float*)d_in[7];
    const float* spat_b   = (const float*)d_in[8];
    const float* temp_w   = (const float*)d_in[9];
    const float* temp_b   = (const float*)d_in[10];
    const float* int_in_w = (const float*)d_in[11];
    const float* int_in_b = (const float*)d_in[12];
    const float* int_out_w= (const float*)d_in[13];
    const float* int_out_b= (const float*)d_in[14];
    const float* ffn_w1   = (const float*)d_in[15];
    const float* ffn_b1   = (const float*)d_in[16];
    const float* ffn_w2   = (const float*)d_in[17];
    const float* ffn_b2   = (const float*)d_in[18];
    const float* ln1_g    = (const float*)d_in[19];
    const float* ln1_b    = (const float*)d_in[20];
    const float* ln2_g    = (const float*)d_in[21];
    const float* ln2_b    = (const float*)d_in[22];
    float* out = (float*)d_out;

    float* f32 = nullptr;
    cudaGetSymbolAddress((void**)&f32, g_f32);

    static cudaStream_t s2 = nullptr;
    static cudaEvent_t evF = nullptr, evJ = nullptr;
    static bool init_done = false;
    if (!init_done) {
        cudaFuncSetAttribute(gemm_tf, cudaFuncAttributeMaxDynamicSharedMemorySize, 2 * GSTT);
        cudaFuncSetAttribute(mcov_tf, cudaFuncAttributeMaxDynamicSharedMemorySize, 2 * CSTT);
        cudaStreamCreateWithFlags(&s2, cudaStreamNonBlocking);
        cudaEventCreateWithFlags(&evF, cudaEventDisableTiming);
        cudaEventCreateWithFlags(&evJ, cudaEventDisableTiming);
        init_done = true;
    }

    float* qkv   = f32 + F_QKV;
    float* qkv2  = f32 + F_QKV2;
    float* att   = f32 + F_ATT;
    float* att2  = f32 + F_ATT2;
    float* bufb  = f32 + F_BUFB;
    float* bufh  = f32 + F_BUFH;
    float* bufc  = f32 + F_BUFC;
    float* se    = f32 + F_SE;
    float* sn    = f32 + F_SN;
    float* te    = f32 + F_TE;
    float* tn    = f32 + F_TN;
    float* bM    = f32 + F_M;
    float* bsim  = f32 + F_SIM;

    #define NP4 nullptr, nullptr, nullptr, nullptr

    // ---- fork ----
    cudaEventRecord(evF, 0);
    cudaStreamWaitEvent(s2, evF, 0);

    // ===== main stream: x-chain =====
    gemm_tf<<<dim3(3, 256), 256, 2 * GSTT>>>(
        x, nullptr, lw_in_w, lw_in_b, qkv, nullptr, NP4,
        nullptr, nullptr, nullptr, nullptr, 128, 384, EP_F32, 0, 0);
    lw_attn_k<<<dim3(64, 8), 256>>>(qkv, att);
    gemm_tf<<<dim3(1, 256), 256, 2 * GSTT>>>(
        att, nullptr, lw_out_w, lw_out_b, bufb, nullptr, NP4,
        x, nullptr, ln1_g, ln1_b, 128, 128, EP_LN, 0, 0);
    gemm_tf<<<dim3(4, 256), 256, 2 * GSTT>>>(
        bufb, nullptr, ffn_w1, ffn_b1, bufh, nullptr, NP4,
        nullptr, nullptr, nullptr, nullptr, 128, 512, EP_GELU, 0, 0);
    gemm_tf<<<dim3(1, 256), 256, 2 * GSTT>>>(
        bufh, nullptr, ffn_w2, ffn_b2, bufc, nullptr, NP4,
        bufb, nullptr, ln2_g, ln2_b, 512, 128, EP_LN2, 0, 0);

    // ===== stream 2: spatio-temporal chain =====
    zero_k<<<512, 256, 0, s2>>>(bM, 8 * 128 * 128);
    gemm_tf<<<dim3(1, 512), 256, 2 * GSTT, s2>>>(
        sp, tp, spat_w, spat_b, sn, se,
        temp_w, temp_b, tn, te,
        nullptr, nullptr, nullptr, nullptr, 128, 128, EP_COS, 0, 256);
    mcov_tf<<<dim3(16, 8), 256, 2 * CSTT, s2>>>(sn, tn, bM);
    gemm_tf<<<dim3(1, 256), 256, 2 * GSTT, s2>>>(
        tn, nullptr, bM, nullptr, bsim, nullptr, NP4,
        sn, nullptr, nullptr, nullptr, 128, 0, EP_SIMDOT, 16384, 0);
    gemm_tf<<<dim3(3, 256), 256, 2 * GSTT, s2>>>(
        se, te, int_in_w, int_in_b, qkv2, nullptr, NP4,
        nullptr, nullptr, nullptr, nullptr, 128, 384, EP_F32, 0, 0);
    int_attn_k<<<512, 256, 0, s2>>>(qkv2, att2);
    cudaEventRecord(evJ, s2);

    // ---- join + final ----
    cudaStreamWaitEvent(0, evJ, 0);
    gemm_tf<<<dim3(1, 256), 256, 2 * GSTT>>>(
        att2, nullptr, int_out_w, int_out_b, out, nullptr, NP4,
        bufc, bsim, nullptr, nullptr, 128, 128, EP_FINAL, 0, 0);
}

// round 15
// speedup vs baseline: 1.0660x; 1.0525x over previous
#include <cuda_runtime.h>
#include <cstdint>
#include <math.h>

#define BB 8
#define SS 2048
#define TT 16384

// ---------------- fp32 scratch ----------------
#define F_QKV  0u            // 16384*384
#define F_QKV2 6291456u      // 16384*384
#define F_ATT  12582912u     // 16384*128
#define F_ATT2 14680064u
#define F_BUFB 16777216u
#define F_BUFH 18874368u     // 16384*512
#define F_BUFC 27262976u
#define F_SE   29360128u
#define F_SN   31457280u
#define F_TE   33554432u
#define F_TN   35651584u
#define F_M    37748736u     // 8*128*128
#define F_SIM  37879808u     // 16384
#define F_TOT  37896192u
__device__ float g_f32[F_TOT];

enum { EP_F32 = 0, EP_LN = 1, EP_GELU = 2, EP_LN2 = 3, EP_COS = 4, EP_FINAL = 5, EP_SIMDOT = 6 };

__device__ __forceinline__ uint32_t smem_to_u32(const void* p) {
    uint32_t a;
    asm("{ .reg .u64 t; cvta.to.shared.u64 t, %1; cvt.u32.u64 %0, t; }" : "=r"(a) : "l"(p));
    return a;
}

#define CP16(dst, src) do { \
    unsigned long long _gs = (unsigned long long)__cvta_generic_to_global((const void*)(src)); \
    asm volatile("cp.async.cg.shared.global [%0], [%1], 16;" :: "r"(dst), "l"(_gs)); } while (0)
#define CP_COMMIT() asm volatile("cp.async.commit_group;" ::: "memory")
#define CP_WAIT(n) asm volatile("cp.async.wait_group %0;" :: "n"(n) : "memory")

// tf32 mma: D(16x8) += A(16x8) * B(8x8); raw f32 regs truncated to tf32 by HW
#define MMA_TF32(c, a, b) \
    asm volatile("mma.sync.aligned.m16n8k8.row.col.f32.tf32.tf32.f32 " \
        "{%0,%1,%2,%3}, {%4,%5,%6,%7}, {%8,%9}, {%0,%1,%2,%3};" \
        : "+f"((c)[0]), "+f"((c)[1]), "+f"((c)[2]), "+f"((c)[3]) \
        : "r"((a)[0]), "r"((a)[1]), "r"((a)[2]), "r"((a)[3]), "r"((b)[0]), "r"((b)[1]))

__device__ __forceinline__ float gelu_f(float v) {
    return 0.5f * v * (1.0f + erff(v * 0.70710678118654752f));
}

__global__ void zero_k(float* p, int n)
{
    int i = blockIdx.x * 256 + threadIdx.x;
    if (i < n) p[i] = 0.f;
}

// ============== generic tf32 GEMM: C[M,N] = A @ W^T ==============
// Tile 64(M) x 128(N), 256 threads = 8 warps (2 wm x 4 wn), warp tile 32x32.
// smem stage (27648B): A +0 (64 rows x 36 floats), B +9216 (128 rows x 36 floats).
// 2-stage single-sync pipeline, running-pointer loaders. Dual-problem optional.
#define GSTT 27648
__global__ void __launch_bounds__(256, 3) gemm_tf(
    const float* __restrict__ A, const float* __restrict__ A2,
    const float* __restrict__ W,
    const float* __restrict__ bias, float* __restrict__ C,
    float* __restrict__ Ct,
    const float* __restrict__ Wd, const float* __restrict__ biasd,
    float* __restrict__ Cd, float* __restrict__ Ctd,
    const float* __restrict__ R, const float* __restrict__ rs,
    const float* __restrict__ gam, const float* __restrict__ bet,
    int K, int ldc, int mode, int batchW, int dualY)
{
    extern __shared__ char smem[];
    float* sf = (float*)smem;
    uint32_t sb = smem_to_u32(smem);
    const int tid = threadIdx.x, lane = tid & 31, wid = tid >> 5;
    const int wm = wid >> 2, wn = wid & 3;
    const int lr = lane >> 2, lc = lane & 3;
    int by = blockIdx.y;
    const int bn = blockIdx.x * 128;

    const float* Au = A;
    if (dualY > 0 && by >= dualY) {
        by -= dualY;
        Au = A2; W = Wd; bias = biasd; C = Cd; Ct = Ctd;
    } else if (dualY == 0 && A2 && bn > 0) {
        Au = A2;
    }
    const int bm = by * 64;
    if (batchW) W += (size_t)(bm >> 11) * (size_t)batchW;

    const int nch = K >> 5;

    float acc[2][4][4];
    #pragma unroll
    for (int i = 0; i < 2; i++)
        #pragma unroll
        for (int j = 0; j < 4; j++)
            #pragma unroll
            for (int k = 0; k < 4; k++) acc[i][j][k] = 0.f;

    const int rowA = tid >> 3, qA = tid & 7;
    // running global pointers (advance 32 floats per chunk)
    const float* gA0 = Au + (size_t)(bm + rowA) * K + qA * 4;
    const float* gA1 = Au + (size_t)(bm + rowA + 32) * K + qA * 4;
    const float* gW0 = W + (size_t)(bn + rowA) * K + qA * 4;
    const float* gW1 = W + (size_t)(bn + rowA + 32) * K + qA * 4;
    const float* gW2 = W + (size_t)(bn + rowA + 64) * K + qA * 4;
    const float* gW3 = W + (size_t)(bn + rowA + 96) * K + qA * 4;
    const uint32_t dA0 = sb + rowA * 144 + qA * 16;
    const uint32_t dA1 = dA0 + 32 * 144;
    const uint32_t dB0 = sb + 9216 + rowA * 144 + qA * 16;
    const uint32_t dB1 = dB0 + 32 * 144;
    const uint32_t dB2 = dB0 + 64 * 144;
    const uint32_t dB3 = dB0 + 96 * 144;

    // prologue: chunk 0 -> stage 0
    CP16(dA0, gA0); CP16(dA1, gA1);
    CP16(dB0, gW0); CP16(dB1, gW1); CP16(dB2, gW2); CP16(dB3, gW3);
    CP_COMMIT();
    gA0 += 32; gA1 += 32; gW0 += 32; gW1 += 32; gW2 += 32; gW3 += 32;

    for (int c = 0; c < nch; c++) {
        CP_WAIT(0);
        __syncthreads();
        if (c + 1 < nch) {
            uint32_t stg = ((c + 1) & 1) * GSTT;
            CP16(dA0 + stg, gA0); CP16(dA1 + stg, gA1);
            CP16(dB0 + stg, gW0); CP16(dB1 + stg, gW1);
            CP16(dB2 + stg, gW2); CP16(dB3 + stg, gW3);
            CP_COMMIT();
            gA0 += 32; gA1 += 32; gW0 += 32; gW1 += 32; gW2 += 32; gW3 += 32;
        }
        const float* tA = sf + (c & 1) * (GSTT / 4);
        const float* tB = tA + 2304;
        #pragma unroll
        for (int ks = 0; ks < 4; ks++) {
            const int ko = ks * 8;
            uint32_t af[2][4], bf[4][2];
            #pragma unroll
            for (int mt = 0; mt < 2; mt++) {
                int r0 = (wm * 32 + mt * 16 + lr) * 36 + ko + lc;
                af[mt][0] = __float_as_uint(tA[r0]);
                af[mt][1] = __float_as_uint(tA[r0 + 8 * 36]);
                af[mt][2] = __float_as_uint(tA[r0 + 4]);
                af[mt][3] = __float_as_uint(tA[r0 + 8 * 36 + 4]);
            }
            #pragma unroll
            for (int nt = 0; nt < 4; nt++) {
                int n0 = (wn * 32 + nt * 8 + lr) * 36 + ko + lc;
                bf[nt][0] = __float_as_uint(tB[n0]);
                bf[nt][1] = __float_as_uint(tB[n0 + 4]);
            }
            #pragma unroll
            for (int mt = 0; mt < 2; mt++)
                #pragma unroll
                for (int nt = 0; nt < 4; nt++)
                    MMA_TF32(acc[mt][nt], af[mt], bf[nt]);
        }
    }
    __syncthreads();

    // ---------------- epilogues ----------------
    if (mode == EP_SIMDOT) {
        float* simS = (float*)smem;
        if (tid < 64) simS[tid] = 0.f;
        __syncthreads();
        #pragma unroll
        for (int mt = 0; mt < 2; mt++) {
            int row0 = bm + wm * 32 + mt * 16 + lr;
            float d0 = 0.f, d1 = 0.f;
            #pragma unroll
            for (int nt = 0; nt < 4; nt++) {
                int col = bn + wn * 32 + nt * 8 + 2 * lc;
                float2 s0 = *(const float2*)(R + (size_t)row0 * 128 + col);
                float2 s1 = *(const float2*)(R + (size_t)(row0 + 8) * 128 + col);
                d0 += acc[mt][nt][0] * s0.x + acc[mt][nt][1] * s0.y;
                d1 += acc[mt][nt][2] * s1.x + acc[mt][nt][3] * s1.y;
            }
            d0 += __shfl_xor_sync(0xffffffffu, d0, 1);
            d0 += __shfl_xor_sync(0xffffffffu, d0, 2);
            d1 += __shfl_xor_sync(0xffffffffu, d1, 1);
            d1 += __shfl_xor_sync(0xffffffffu, d1, 2);
            if (lc == 0) {
                atomicAdd(&simS[wm * 32 + mt * 16 + lr], d0);
                atomicAdd(&simS[wm * 32 + mt * 16 + lr + 8], d1);
            }
        }
        __syncthreads();
        if (tid < 64) C[bm + tid] = simS[tid] * (1.f / 2048.f);
        return;
    }

    #pragma unroll
    for (int mt = 0; mt < 2; mt++) {
        int row = bm + wm * 32 + mt * 16 + lr;
        #pragma unroll
        for (int nt = 0; nt < 4; nt++) {
            int col = bn + wn * 32 + nt * 8 + 2 * lc;
            float2 b2 = *(const float2*)(bias + col);
            float* a = acc[mt][nt];
            a[0] += b2.x; a[1] += b2.y; a[2] += b2.x; a[3] += b2.y;
            if (mode == EP_LN || mode == EP_LN2) {
                float2 r0 = *(const float2*)(R + (size_t)row * ldc + col);
                float2 r1 = *(const float2*)(R + (size_t)(row + 8) * ldc + col);
                a[0] += r0.x; a[1] += r0.y; a[2] += r1.x; a[3] += r1.y;
            } else if (mode == EP_GELU) {
                a[0] = gelu_f(a[0]); a[1] = gelu_f(a[1]);
                a[2] = gelu_f(a[2]); a[3] = gelu_f(a[3]);
            } else if (mode == EP_FINAL) {
                float2 r0 = *(const float2*)(R + (size_t)row * ldc + col);
                float2 r1 = *(const float2*)(R + (size_t)(row + 8) * ldc + col);
                float sc0 = rs[row], sc1 = rs[row + 8];
                a[0] = r0.x + sc0 * a[0]; a[1] = r0.y + sc0 * a[1];
                a[2] = r1.x + sc1 * a[2]; a[3] = r1.y + sc1 * a[3];
            }
        }
    }

    if (mode == EP_LN || mode == EP_LN2 || mode == EP_COS) {
        float* ps = (float*)smem;        // [64][4]
        float* ps2 = ps + 256;
        #pragma unroll
        for (int mt = 0; mt < 2; mt++) {
            float p0 = 0.f, p1 = 0.f, q0 = 0.f, q1 = 0.f;
            #pragma unroll
            for (int nt = 0; nt < 4; nt++) {
                float* a = acc[mt][nt];
                p0 += a[0] + a[1]; q0 += a[0] * a[0] + a[1] * a[1];
                p1 += a[2] + a[3]; q1 += a[2] * a[2] + a[3] * a[3];
            }
            p0 += __shfl_xor_sync(0xffffffffu, p0, 1); p0 += __shfl_xor_sync(0xffffffffu, p0, 2);
            p1 += __shfl_xor_sync(0xffffffffu, p1, 1); p1 += __shfl_xor_sync(0xffffffffu, p1, 2);
            q0 += __shfl_xor_sync(0xffffffffu, q0, 1); q0 += __shfl_xor_sync(0xffffffffu, q0, 2);
            q1 += __shfl_xor_sync(0xffffffffu, q1, 1); q1 += __shfl_xor_sync(0xffffffffu, q1, 2);
            if (lc == 0) {
                int r0l = wm * 32 + mt * 16 + lr;
                ps[r0l * 4 + wn] = p0; ps2[r0l * 4 + wn] = q0;
                ps[(r0l + 8) * 4 + wn] = p1; ps2[(r0l + 8) * 4 + wn] = q1;
            }
        }
        __syncthreads();
        #pragma unroll
        for (int mt = 0; mt < 2; mt++) {
            int r0l = wm * 32 + mt * 16 + lr;
            float s0 = 0.f, t0 = 0.f, s1 = 0.f, t1 = 0.f;
            #pragma unroll
            for (int w4 = 0; w4 < 4; w4++) {
                s0 += ps[r0l * 4 + w4]; t0 += ps2[r0l * 4 + w4];
                s1 += ps[(r0l + 8) * 4 + w4]; t1 += ps2[(r0l + 8) * 4 + w4];
            }
            int row0 = bm + r0l;
            if (mode == EP_COS) {
                float i0 = 1.f / fmaxf(sqrtf(t0), 1e-8f);
                float i1 = 1.f / fmaxf(sqrtf(t1), 1e-8f);
                #pragma unroll
                for (int nt = 0; nt < 4; nt++) {
                    int col = bn + wn * 32 + nt * 8 + 2 * lc;
                    float* a = acc[mt][nt];
                    size_t i0x = (size_t)row0 * ldc + col, i1x = (size_t)(row0 + 8) * ldc + col;
                    *(float2*)(Ct + i0x) = make_float2(a[0], a[1]);   // raw embed
                    *(float2*)(Ct + i1x) = make_float2(a[2], a[3]);
                    *(float2*)(C + i0x) = make_float2(a[0] * i0, a[1] * i0);  // normalized
                    *(float2*)(C + i1x) = make_float2(a[2] * i1, a[3] * i1);
                }
            } else {
                float mu0 = s0 * (1.f / 128.f), mu1 = s1 * (1.f / 128.f);
                float rs0 = rsqrtf(t0 * (1.f / 128.f) - mu0 * mu0 + 1e-5f);
                float rs1 = rsqrtf(t1 * (1.f / 128.f) - mu1 * mu1 + 1e-5f);
                #pragma unroll
                for (int nt = 0; nt < 4; nt++) {
                    int col = bn + wn * 32 + nt * 8 + 2 * lc;
                    float* a = acc[mt][nt];
                    float2 g2 = *(const float2*)(gam + col);
                    float2 be2 = *(const float2*)(bet + col);
                    float w0 = (a[0] - mu0) * rs0 * g2.x + be2.x;
                    float w1 = (a[1] - mu0) * rs0 * g2.y + be2.y;
                    float w2 = (a[2] - mu1) * rs1 * g2.x + be2.x;
                    float w3 = (a[3] - mu1) * rs1 * g2.y + be2.y;
                    size_t i0x = (size_t)row0 * ldc + col, i1x = (size_t)(row0 + 8) * ldc + col;
                    *(float2*)(C + i0x) = make_float2(w0, w1);
                    *(float2*)(C + i1x) = make_float2(w2, w3);
                }
            }
        }
    } else {
        #pragma unroll
        for (int mt = 0; mt < 2; mt++) {
            int row = bm + wm * 32 + mt * 16 + lr;
            #pragma unroll
            for (int nt = 0; nt < 4; nt++) {
                int col = bn + wn * 32 + nt * 8 + 2 * lc;
                float* a = acc[mt][nt];
                size_t i0x = (size_t)row * ldc + col, i1x = (size_t)(row + 8) * ldc + col;
                *(float2*)(C + i0x) = make_float2(a[0], a[1]);
                *(float2*)(C + i1x) = make_float2(a[2], a[3]);
            }
        }
    }
}

// ============== M covariance: M[b] += sn^T tn (contract over s) ==============
// Tiles stored [s][d]: 32 rows x 132 floats (528B stride). 2-stage single-sync.
#define CSTT 33792
__global__ void __launch_bounds__(256, 2) mcov_tf(
    const float* __restrict__ sn, const float* __restrict__ tn, float* __restrict__ M)
{
    extern __shared__ char smem[];
    float* sf = (float*)smem;
    uint32_t sb = smem_to_u32(smem);
    const int tid = threadIdx.x, lane = tid & 31, wid = tid >> 5;
    const int wm = wid >> 2, wn = wid & 3;
    const int lr = lane >> 2, lc = lane & 3;
    const int b = blockIdx.y, split = blockIdx.x;
    const size_t srow0 = (size_t)b * SS + split * 128;

    float acc[4][4][4];
    #pragma unroll
    for (int i = 0; i < 4; i++)
        #pragma unroll
        for (int j = 0; j < 4; j++)
            #pragma unroll
            for (int k = 0; k < 4; k++) acc[i][j][k] = 0.f;

    const int rowL = tid >> 5, qL = tid & 31;
    const float* gS0 = sn + (srow0 + rowL) * 128 + qL * 4;
    const float* gT0 = tn + (srow0 + rowL) * 128 + qL * 4;
    const uint32_t dS0 = sb + rowL * 528 + qL * 16;
    const uint32_t dT0 = sb + 16896 + rowL * 528 + qL * 16;

    #pragma unroll
    for (int j = 0; j < 4; j++) {
        CP16(dS0 + j * 8 * 528, gS0 + (size_t)j * 8 * 128);
        CP16(dT0 + j * 8 * 528, gT0 + (size_t)j * 8 * 128);
    }
    CP_COMMIT();

    for (int c = 0; c < 4; c++) {
        CP_WAIT(0);
        __syncthreads();
        if (c + 1 < 4) {
            uint32_t stg = ((c + 1) & 1) * CSTT;
            const size_t go = (size_t)(c + 1) * 32 * 128;
            #pragma unroll
            for (int j = 0; j < 4; j++) {
                CP16(dS0 + stg + j * 8 * 528, gS0 + go + (size_t)j * 8 * 128);
                CP16(dT0 + stg + j * 8 * 528, gT0 + go + (size_t)j * 8 * 128);
            }
            CP_COMMIT();
        }
        const float* tS = sf + (c & 1) * (CSTT / 4);
        const float* tT = tS + 4224;
        #pragma unroll
        for (int ks = 0; ks < 4; ks++) {
            const int ko = ks * 8;
            uint32_t af[4][4], bf[4][2];
            #pragma unroll
            for (int mt = 0; mt < 4; mt++) {
                int d0 = wm * 64 + mt * 16 + lr;
                af[mt][0] = __float_as_uint(tS[(ko + lc) * 132 + d0]);
                af[mt][1] = __float_as_uint(tS[(ko + lc) * 132 + d0 + 8]);
                af[mt][2] = __float_as_uint(tS[(ko + lc + 4) * 132 + d0]);
                af[mt][3] = __float_as_uint(tS[(ko + lc + 4) * 132 + d0 + 8]);
            }
            #pragma unroll
            for (int nt = 0; nt < 4; nt++) {
                int e0 = wn * 32 + nt * 8 + lr;
                bf[nt][0] = __float_as_uint(tT[(ko + lc) * 132 + e0]);
                bf[nt][1] = __float_as_uint(tT[(ko + lc + 4) * 132 + e0]);
            }
            #pragma unroll
            for (int mt = 0; mt < 4; mt++)
                #pragma unroll
                for (int nt = 0; nt < 4; nt++)
                    MMA_TF32(acc[mt][nt], af[mt], bf[nt]);
        }
    }

    float* Mb = M + (size_t)b * 16384;
    #pragma unroll
    for (int mt = 0; mt < 4; mt++) {
        int row = wm * 64 + mt * 16 + lr;
        #pragma unroll
        for (int nt = 0; nt < 4; nt++) {
            int col = wn * 32 + nt * 8 + 2 * lc;
            atomicAdd(&Mb[(size_t)row * 128 + col], acc[mt][nt][0]);
            atomicAdd(&Mb[(size_t)row * 128 + col + 1], acc[mt][nt][1]);
            atomicAdd(&Mb[(size_t)(row + 8) * 128 + col], acc[mt][nt][2]);
            atomicAdd(&Mb[(size_t)(row + 8) * 128 + col + 1], acc[mt][nt][3]);
        }
    }
}

// ---------------- local windowed causal attention ----------------
__global__ __launch_bounds__(64) void lw_attn_k(const float* __restrict__ qkv,
                                                float* __restrict__ outp)
{
    int g = blockIdx.x, h = blockIdx.y, i = threadIdx.x;
    __shared__ float ks[64][17];
    __shared__ float vs[64][17];
    size_t tbase = (size_t)g * 64;
    const float* kp = qkv + (tbase + i) * 384 + 128 + h * 16;
    const float* vp = kp + 128;
    #pragma unroll
    for (int d = 0; d < 16; d++) { ks[i][d] = kp[d]; vs[i][d] = vp[d]; }
    float q[16];
    const float* qp = qkv + (tbase + i) * 384 + h * 16;
    #pragma unroll
    for (int d = 0; d < 16; d++) q[d] = qp[d];
    __syncthreads();
    float sc[64];
    float mx = -1e30f;
    #pragma unroll
    for (int j = 0; j < 64; j++) {
        float dv = 0.f;
        #pragma unroll
        for (int d = 0; d < 16; d++) dv += q[d] * ks[j][d];
        sc[j] = (j <= i) ? dv * 0.25f : -INFINITY;
        mx = fmaxf(mx, sc[j]);
    }
    float sum = 0.f;
    #pragma unroll
    for (int j = 0; j < 64; j++) { float e = expf(sc[j] - mx); sc[j] = e; sum += e; }
    float o[16] = {};
    #pragma unroll
    for (int j = 0; j < 64; j++) {
        float w = sc[j];
        #pragma unroll
        for (int d = 0; d < 16; d++) o[d] += w * vs[j][d];
    }
    float inv = 1.f / sum;
    float* op = outp + (tbase + i) * 128 + h * 16;
    #pragma unroll
    for (int d = 0; d < 16; d++) op[d] = o[d] * inv;
}

// ---------------- interaction MHA (len = B = 8) ----------------
__global__ __launch_bounds__(64) void int_attn_k(const float* __restrict__ qkv,
                                                 float* __restrict__ outp)
{
    int s = blockIdx.x, tid = threadIdx.x;
    __shared__ float kvs[8][256];
    for (int idx = tid; idx < 8 * 256; idx += 64) {
        int jb = idx >> 8, c = idx & 255;
        kvs[jb][c] = qkv[((size_t)jb * SS + s) * 384 + 128 + c];
    }
    __syncthreads();
    int h = tid >> 3, qb = tid & 7;
    float q[16];
    const float* qp = qkv + ((size_t)qb * SS + s) * 384 + h * 16;
    #pragma unroll
    for (int d = 0; d < 16; d++) q[d] = qp[d];
    float sc[8];
    float mx = -1e30f;
    #pragma unroll
    for (int jb = 0; jb < 8; jb++) {
        float dv = 0.f;
        #pragma unroll
        for (int d = 0; d < 16; d++) dv += q[d] * kvs[jb][h * 16 + d];
        sc[jb] = dv * 0.25f;
        mx = fmaxf(mx, sc[jb]);
    }
    float sum = 0.f;
    #pragma unroll
    for (int jb = 0; jb < 8; jb++) { float e = expf(sc[jb] - mx); sc[jb] = e; sum += e; }
    float o[16] = {};
    #pragma unroll
    for (int jb = 0; jb < 8; jb++) {
        float w = sc[jb];
        #pragma unroll
        for (int d = 0; d < 16; d++) o[d] += w * kvs[jb][128 + h * 16 + d];
    }
    float inv = 1.f / sum;
    float* op = outp + ((size_t)qb * SS + s) * 128 + h * 16;
    #pragma unroll
    for (int d = 0; d < 16; d++) op[d] = o[d] * inv;
}

extern "C" void kernel_launch(void* const* d_in, const int* in_sizes, int n_in,
                              void* d_out, int out_size)
{
    const float* x        = (const float*)d_in[0];
    const float* sp       = (const float*)d_in[1];
    const float* tp       = (const float*)d_in[2];
    const float* lw_in_w  = (const float*)d_in[3];
    const float* lw_in_b  = (const float*)d_in[4];
    const float* lw_out_w = (const float*)d_in[5];
    const float* lw_out_b = (const float*)d_in[6];
    const float* spat_w   = (const float*)d_in[7];
    const float* spat_b   = (const float*)d_in[8];
    const float* temp_w   = (const float*)d_in[9];
    const float* temp_b   = (const float*)d_in[10];
    const float* int_in_w = (const float*)d_in[11];
    const float* int_in_b = (const float*)d_in[12];
    const float* int_out_w= (const float*)d_in[13];
    const float* int_out_b= (const float*)d_in[14];
    const float* ffn_w1   = (const float*)d_in[15];
    const float* ffn_b1   = (const float*)d_in[16];
    const float* ffn_w2   = (const float*)d_in[17];
    const float* ffn_b2   = (const float*)d_in[18];
    const float* ln1_g    = (const float*)d_in[19];
    const float* ln1_b    = (const float*)d_in[20];
    const float* ln2_g    = (const float*)d_in[21];
    const float* ln2_b    = (const float*)d_in[22];
    float* out = (float*)d_out;

    float* f32 = nullptr;
    cudaGetSymbolAddress((void**)&f32, g_f32);

    static cudaStream_t s2 = nullptr;
    static cudaEvent_t evF = nullptr, evJ = nullptr;
    static bool init_done = false;
    if (!init_done) {
        cudaFuncSetAttribute(gemm_tf, cudaFuncAttributeMaxDynamicSharedMemorySize, 2 * GSTT);
        cudaFuncSetAttribute(mcov_tf, cudaFuncAttributeMaxDynamicSharedMemorySize, 2 * CSTT);
        cudaStreamCreateWithFlags(&s2, cudaStreamNonBlocking);
        cudaEventCreateWithFlags(&evF, cudaEventDisableTiming);
        cudaEventCreateWithFlags(&evJ, cudaEventDisableTiming);
        init_done = true;
    }

    float* qkv   = f32 + F_QKV;
    float* qkv2  = f32 + F_QKV2;
    float* att   = f32 + F_ATT;
    float* att2  = f32 + F_ATT2;
    float* bufb  = f32 + F_BUFB;
    float* bufh  = f32 + F_BUFH;
    float* bufc  = f32 + F_BUFC;
    float* se    = f32 + F_SE;
    float* sn    = f32 + F_SN;
    float* te    = f32 + F_TE;
    float* tn    = f32 + F_TN;
    float* bM    = f32 + F_M;
    float* bsim  = f32 + F_SIM;

    #define NP4 nullptr, nullptr, nullptr, nullptr

    // ---- fork ----
    cudaEventRecord(evF, 0);
    cudaStreamWaitEvent(s2, evF, 0);

    // ===== main stream: x-chain =====
    gemm_tf<<<dim3(3, 256), 256, 2 * GSTT>>>(
        x, nullptr, lw_in_w, lw_in_b, qkv, nullptr, NP4,
        nullptr, nullptr, nullptr, nullptr, 128, 384, EP_F32, 0, 0);
    lw_attn_k<<<dim3(256, 8), 64>>>(qkv, att);
    gemm_tf<<<dim3(1, 256), 256, 2 * GSTT>>>(
        att, nullptr, lw_out_w, lw_out_b, bufb, nullptr, NP4,
        x, nullptr, ln1_g, ln1_b, 128, 128, EP_LN, 0, 0);
    gemm_tf<<<dim3(4, 256), 256, 2 * GSTT>>>(
        bufb, nullptr, ffn_w1, ffn_b1, bufh, nullptr, NP4,
        nullptr, nullptr, nullptr, nullptr, 128, 512, EP_GELU, 0, 0);
    gemm_tf<<<dim3(1, 256), 256, 2 * GSTT>>>(
        bufh, nullptr, ffn_w2, ffn_b2, bufc, nullptr, NP4,
        bufb, nullptr, ln2_g, ln2_b, 512, 128, EP_LN2, 0, 0);

    // ===== stream 2: spatio-temporal chain =====
    zero_k<<<512, 256, 0, s2>>>(bM, 8 * 128 * 128);
    gemm_tf<<<dim3(1, 512), 256, 2 * GSTT, s2>>>(
        sp, tp, spat_w, spat_b, sn, se,
        temp_w, temp_b, tn, te,
        nullptr, nullptr, nullptr, nullptr, 128, 128, EP_COS, 0, 256);
    mcov_tf<<<dim3(16, 8), 256, 2 * CSTT, s2>>>(sn, tn, bM);
    gemm_tf<<<dim3(1, 256), 256, 2 * GSTT, s2>>>(
        tn, nullptr, bM, nullptr, bsim, nullptr, NP4,
        sn, nullptr, nullptr, nullptr, 128, 0, EP_SIMDOT, 16384, 0);
    gemm_tf<<<dim3(3, 256), 256, 2 * GSTT, s2>>>(
        se, te, int_in_w, int_in_b, qkv2, nullptr, NP4,
        nullptr, nullptr, nullptr, nullptr, 128, 384, EP_F32, 0, 0);
    int_attn_k<<<SS, 64, 0, s2>>>(qkv2, att2);
    cudaEventRecord(evJ, s2);

    // ---- join + final ----
    cudaStreamWaitEvent(0, evJ, 0);
    gemm_tf<<<dim3(1, 256), 256, 2 * GSTT>>>(
        att2, nullptr, int_out_w, int_out_b, out, nullptr, NP4,
        bufc, bsim, nullptr, nullptr, 128, 128, EP_FINAL, 0, 0);
}